// round 4
// baseline (speedup 1.0000x reference)
#include <cuda_runtime.h>

// out = cumprod_j( cos(w_j) * cos(x @ W_pre^T + b_pre) ) @ W_post^T + b_post
//
// Analytic reduction of the quantum layer:
//   z_j   = cos(q_weights_j) * cos(angle_j)
//   <Z_i> = prod_{j<=i} z_j            (CNOT chain = prefix-XOR)
//
// Single fused kernel, one block per batch row, 512 threads (16 warps).
//   - x row staged to smem once (kills 16x redundant x reads)
//   - W_post/b_post prefetched to registers before the first barrier
//   - warp j: angle_j via 8 LDG(W_pre) + 8 LDS(x) + warp reduce
//   - warp 0: __cosf + shfl_up inclusive prefix product
//   - each thread: 2 outputs from register W_post, float2 store

#define NQ   16
#define DIN  1024
#define DOUT 1024
#define B    256

__global__ __launch_bounds__(512, 2)
void quantum_projector_kernel(const float* __restrict__ x,
                              const float* __restrict__ W_pre,
                              const float* __restrict__ b_pre,
                              const float* __restrict__ q_weights,
                              const float* __restrict__ W_post,
                              const float* __restrict__ b_post,
                              float* __restrict__ out)
{
    __shared__ float4 sx[DIN / 4];     // 4 KB: one x row
    __shared__ float  s_angle[NQ];
    __shared__ float  s_zq[NQ];

    const int row  = blockIdx.x;
    const int tid  = threadIdx.x;
    const int warp = tid >> 5;         // 16 warps = 16 qubits
    const int lane = tid & 31;

    // ---- Stage x row into smem (256 float4, threads 0..255) ----
    const float4* __restrict__ x4 = reinterpret_cast<const float4*>(x + row * DIN);
    if (tid < DIN / 4)
        sx[tid] = x4[tid];

    // ---- Prefetch phase-3 operands early (latency hides under stage+phase1) ----
    // Thread t covers outputs o0=2t, o1=2t+1: W_post rows = float4[8t .. 8t+7]
    const float4* __restrict__ Wp4 = reinterpret_cast<const float4*>(W_post);
    float4 wreg[8];
#pragma unroll
    for (int i = 0; i < 8; i++)
        wreg[i] = Wp4[8 * tid + i];
    const float2 bp = reinterpret_cast<const float2*>(b_post)[tid];

    __syncthreads();

    // ---- Phase 1: angle[warp] = dot(sx, W_pre[warp,:]) + b_pre[warp] ----
    {
        const float4* __restrict__ w4 = reinterpret_cast<const float4*>(W_pre + warp * DIN);
        float acc = 0.f;
#pragma unroll
        for (int i = 0; i < 8; i++) {
            const int k = lane + 32 * i;       // 256 float4, 8 per lane
            float4 wv = w4[k];
            float4 xv = sx[k];
            acc += xv.x * wv.x + xv.y * wv.y + xv.z * wv.z + xv.w * wv.w;
        }
#pragma unroll
        for (int off = 16; off >= 1; off >>= 1)
            acc += __shfl_xor_sync(0xffffffffu, acc, off);

        if (lane == 0)
            s_angle[warp] = acc + b_pre[warp];
    }
    __syncthreads();

    // ---- Phase 2: warp 0: zq = inclusive prefix product of __cosf terms ----
    if (warp == 0) {
        float v = 1.f;
        if (lane < NQ)
            v = __cosf(q_weights[lane]) * __cosf(s_angle[lane]);
#pragma unroll
        for (int off = 1; off <= 8; off <<= 1) {
            float t = __shfl_up_sync(0xffffffffu, v, off);
            if (lane >= off) v *= t;
        }
        if (lane < NQ)
            s_zq[lane] = v;
    }
    __syncthreads();

    // ---- Phase 3: two outputs per thread from register W_post ----
    float zq[NQ];
#pragma unroll
    for (int j = 0; j < NQ; j++) zq[j] = s_zq[j];

    float d0 = zq[0]  * wreg[0].x + zq[1]  * wreg[0].y + zq[2]  * wreg[0].z + zq[3]  * wreg[0].w
             + zq[4]  * wreg[1].x + zq[5]  * wreg[1].y + zq[6]  * wreg[1].z + zq[7]  * wreg[1].w
             + zq[8]  * wreg[2].x + zq[9]  * wreg[2].y + zq[10] * wreg[2].z + zq[11] * wreg[2].w
             + zq[12] * wreg[3].x + zq[13] * wreg[3].y + zq[14] * wreg[3].z + zq[15] * wreg[3].w;
    float d1 = zq[0]  * wreg[4].x + zq[1]  * wreg[4].y + zq[2]  * wreg[4].z + zq[3]  * wreg[4].w
             + zq[4]  * wreg[5].x + zq[5]  * wreg[5].y + zq[6]  * wreg[5].z + zq[7]  * wreg[5].w
             + zq[8]  * wreg[6].x + zq[9]  * wreg[6].y + zq[10] * wreg[6].z + zq[11] * wreg[6].w
             + zq[12] * wreg[7].x + zq[13] * wreg[7].y + zq[14] * wreg[7].z + zq[15] * wreg[7].w;

    reinterpret_cast<float2*>(out + row * DOUT)[tid] = make_float2(bp.x + d0, bp.y + d1);
}

extern "C" void kernel_launch(void* const* d_in, const int* in_sizes, int n_in,
                              void* d_out, int out_size)
{
    const float* x         = (const float*)d_in[0];   // [256, 1024]
    const float* W_pre     = (const float*)d_in[1];   // [16, 1024]
    const float* b_pre     = (const float*)d_in[2];   // [16]
    const float* q_weights = (const float*)d_in[3];   // [16]
    const float* W_post    = (const float*)d_in[4];   // [1024, 16]
    const float* b_post    = (const float*)d_in[5];   // [1024]
    float* out             = (float*)d_out;           // [256, 1024]

    quantum_projector_kernel<<<B, 512>>>(x, W_pre, b_pre, q_weights,
                                         W_post, b_post, out);
}

// round 6
// speedup vs baseline: 1.1831x; 1.1831x over previous
#include <cuda_runtime.h>

// out = cumprod_j( cos(w_j) * cos(x @ W_pre^T + b_pre) ) @ W_post^T + b_post
//
// Analytic reduction of the quantum layer:
//   z_j   = cos(q_weights_j) * cos(angle_j)
//   <Z_i> = prod_{j<=i} z_j            (CNOT chain = prefix-XOR)
//
// TWO ROWS PER BLOCK: weights (W_pre row + W_post slice) loaded into registers
// once and reused for both rows -> per-SM L1tex traffic ~halves.
// grid=128 blocks x 512 threads, 1 block/SM.

#define NQ   16
#define DIN  1024
#define DOUT 1024
#define B    256

__forceinline__ __device__
float dot16(const float* __restrict__ zz,
            const float4& a, const float4& b, const float4& c, const float4& d)
{
    return zz[0]  * a.x + zz[1]  * a.y + zz[2]  * a.z + zz[3]  * a.w
         + zz[4]  * b.x + zz[5]  * b.y + zz[6]  * b.z + zz[7]  * b.w
         + zz[8]  * c.x + zz[9]  * c.y + zz[10] * c.z + zz[11] * c.w
         + zz[12] * d.x + zz[13] * d.y + zz[14] * d.z + zz[15] * d.w;
}

__global__ __launch_bounds__(512, 1)
void quantum_projector_kernel(const float* __restrict__ x,
                              const float* __restrict__ W_pre,
                              const float* __restrict__ b_pre,
                              const float* __restrict__ q_weights,
                              const float* __restrict__ W_post,
                              const float* __restrict__ b_post,
                              float* __restrict__ out)
{
    __shared__ float4 sx0[DIN / 4];    // 4 KB: row r0
    __shared__ float4 sx1[DIN / 4];    // 4 KB: row r1
    __shared__ float  s_angle[2 * NQ]; // [row][qubit]
    __shared__ float  s_zq[2 * NQ];

    const int r0   = blockIdx.x * 2;
    const int r1   = r0 + 1;
    const int tid  = threadIdx.x;
    const int warp = tid >> 5;         // 16 warps = 16 qubits
    const int lane = tid & 31;

    // ---- Stage both x rows into smem (512 threads, one float4 each) ----
    {
        const float4* __restrict__ x4 = reinterpret_cast<const float4*>(x);
        if (tid < 256) sx0[tid]       = x4[r0 * (DIN / 4) + tid];
        else           sx1[tid - 256] = x4[r1 * (DIN / 4) + (tid - 256)];
    }

    // ---- Weight prefetch into registers (shared by both rows) ----
    const float4* __restrict__ w4 = reinterpret_cast<const float4*>(W_pre + warp * DIN);
    float4 wv[8];
#pragma unroll
    for (int i = 0; i < 8; i++)
        wv[i] = w4[lane + 32 * i];

    // Thread t covers output cols o0=2t, o1=2t+1 (same cols for both rows).
    const float4* __restrict__ Wp4 = reinterpret_cast<const float4*>(W_post);
    float4 wreg[8];
#pragma unroll
    for (int i = 0; i < 8; i++)
        wreg[i] = Wp4[8 * tid + i];
    const float2 bp = reinterpret_cast<const float2*>(b_post)[tid];

    __syncthreads();

    // ---- Phase 1: both rows' angle[warp], interleaved for ILP ----
    {
        float acc0 = 0.f, acc1 = 0.f;
#pragma unroll
        for (int i = 0; i < 8; i++) {
            const int k = lane + 32 * i;
            float4 xv0 = sx0[k];
            float4 xv1 = sx1[k];
            acc0 += xv0.x * wv[i].x + xv0.y * wv[i].y + xv0.z * wv[i].z + xv0.w * wv[i].w;
            acc1 += xv1.x * wv[i].x + xv1.y * wv[i].y + xv1.z * wv[i].z + xv1.w * wv[i].w;
        }
#pragma unroll
        for (int off = 16; off >= 1; off >>= 1) {
            acc0 += __shfl_xor_sync(0xffffffffu, acc0, off);
            acc1 += __shfl_xor_sync(0xffffffffu, acc1, off);
        }
        if (lane == 0) {
            const float b = b_pre[warp];
            s_angle[warp]      = acc0 + b;
            s_angle[NQ + warp] = acc1 + b;
        }
    }
    __syncthreads();

    // ---- Phase 2: warp 0 does BOTH rows' prefix products ----
    // lanes 0..15 -> row0, lanes 16..31 -> row1 (segmented shfl_up scan)
    if (warp == 0) {
        const int q = lane & 15;
        float v = __cosf(q_weights[q]) * __cosf(s_angle[(lane >> 4) * NQ + q]);
#pragma unroll
        for (int off = 1; off <= 8; off <<= 1) {
            float t = __shfl_up_sync(0xffffffffu, v, off);
            if (q >= off) v *= t;          // segment boundary at lane 16: q<off blocks
        }
        s_zq[(lane >> 4) * NQ + q] = v;
    }
    __syncthreads();

    // ---- Phase 3: 2 cols x 2 rows per thread from register W_post ----
    float z0[NQ], z1[NQ];
#pragma unroll
    for (int j = 0; j < NQ; j++) { z0[j] = s_zq[j]; z1[j] = s_zq[NQ + j]; }

    float d00 = dot16(z0, wreg[0], wreg[1], wreg[2], wreg[3]);
    float d01 = dot16(z0, wreg[4], wreg[5], wreg[6], wreg[7]);
    float d10 = dot16(z1, wreg[0], wreg[1], wreg[2], wreg[3]);
    float d11 = dot16(z1, wreg[4], wreg[5], wreg[6], wreg[7]);

    float2* __restrict__ o0 = reinterpret_cast<float2*>(out + r0 * DOUT);
    float2* __restrict__ o1 = reinterpret_cast<float2*>(out + r1 * DOUT);
    o0[tid] = make_float2(bp.x + d00, bp.y + d01);
    o1[tid] = make_float2(bp.x + d10, bp.y + d11);
}

extern "C" void kernel_launch(void* const* d_in, const int* in_sizes, int n_in,
                              void* d_out, int out_size)
{
    const float* x         = (const float*)d_in[0];   // [256, 1024]
    const float* W_pre     = (const float*)d_in[1];   // [16, 1024]
    const float* b_pre     = (const float*)d_in[2];   // [16]
    const float* q_weights = (const float*)d_in[3];   // [16]
    const float* W_post    = (const float*)d_in[4];   // [1024, 16]
    const float* b_post    = (const float*)d_in[5];   // [1024]
    float* out             = (float*)d_out;           // [256, 1024]

    quantum_projector_kernel<<<B / 2, 512>>>(x, W_pre, b_pre, q_weights,
                                             W_post, b_post, out);
}